// round 3
// baseline (speedup 1.0000x reference)
#include <cuda_runtime.h>
#include <cuda_bf16.h>
#include <cstdint>

#define EPS_ 1e-4f

#define B_     2048
#define N_     64
#define E_     512
#define C_     6
#define CN_    7
#define K_     20
#define DSELF_ 120
#define DNEI_  48
#define ROWS_  (B_ * N_)        /* 131072 */
#define XSIZE_ (B_ * K_ * E_)   /* 20971520 */

#define MAXTILES_ 1032

// ---------------- device scratch (no allocations allowed) ----------------
__device__ float g_anchor[C_ * K_ * E_];     // [c,k,e]
__device__ int   g_cnt[CN_];
__device__ int   g_idx[CN_ * ROWS_];
__device__ int   g_nt;
__device__ int2  g_tile[MAXTILES_];          // (class, base)
// pre-split bf16 weights, [c][k][e] layout
__device__ __nv_bfloat16 g_Bhi[CN_ * DNEI_ * E_];
__device__ __nv_bfloat16 g_Blo[CN_ * DNEI_ * E_];

// ---------------- helpers ----------------
__device__ __forceinline__ uint32_t smem_u32(const void* p) {
    uint32_t a;
    asm("{ .reg .u64 t; cvta.to.shared.u64 t, %1; cvt.u32.u64 %0, t; }" : "=r"(a) : "l"(p));
    return a;
}
__device__ __forceinline__ float srecip(float x) {
    float d = x + (x >= 0.0f ? EPS_ : -EPS_);
    return __fdividef(1.0f, d);
}
__device__ __forceinline__ void ldsm4(uint32_t (&r)[4], uint32_t addr) {
    asm volatile("ldmatrix.sync.aligned.m8n8.x4.shared.b16 {%0,%1,%2,%3}, [%4];"
                 : "=r"(r[0]), "=r"(r[1]), "=r"(r[2]), "=r"(r[3]) : "r"(addr));
}
__device__ __forceinline__ void ldsm4t(uint32_t (&r)[4], uint32_t addr) {
    asm volatile("ldmatrix.sync.aligned.m8n8.x4.trans.shared.b16 {%0,%1,%2,%3}, [%4];"
                 : "=r"(r[0]), "=r"(r[1]), "=r"(r[2]), "=r"(r[3]) : "r"(addr));
}
__device__ __forceinline__ void mma_bf16(float (&d)[4], const uint32_t (&a)[4],
                                         uint32_t b0, uint32_t b1) {
    asm volatile("mma.sync.aligned.m16n8k16.row.col.f32.bf16.bf16.f32 "
                 "{%0,%1,%2,%3}, {%4,%5,%6,%7}, {%8,%9}, {%0,%1,%2,%3};"
                 : "+f"(d[0]), "+f"(d[1]), "+f"(d[2]), "+f"(d[3])
                 : "r"(a[0]), "r"(a[1]), "r"(a[2]), "r"(a[3]), "r"(b0), "r"(b1));
}

// ---------------- kernel 1: anchors (+ zero counters) ----------------
__global__ void k_anchor(const float* __restrict__ it,
                         const float* __restrict__ Ws,
                         const float* __restrict__ bs) {
    if (blockIdx.x == 0 && threadIdx.x < CN_) g_cnt[threadIdx.x] = 0;
    __shared__ float its[72];
    int ck = blockIdx.x;
    int c  = ck / K_;
    int t  = threadIdx.x;
    if (t < 18) ((float4*)its)[t] = ((const float4*)(it + ck * 72))[t];
    __syncthreads();
    const float* W = Ws + c * DSELF_ * E_ + 48 * E_ + t;
    float a0 = 0.f, a1 = 0.f, a2 = 0.f, a3 = 0.f;
#pragma unroll
    for (int j = 0; j < 72; j += 4) {
        a0 += its[j + 0] * W[(j + 0) * E_];
        a1 += its[j + 1] * W[(j + 1) * E_];
        a2 += its[j + 2] * W[(j + 2) * E_];
        a3 += its[j + 3] * W[(j + 3) * E_];
    }
    g_anchor[ck * E_ + t] = (a0 + a1) + (a2 + a3) + bs[c * E_ + t];
}

// ---------------- kernel 2: bucket rows by neighbor label ----------------
__global__ void k_bucket(const int* __restrict__ lab) {
    __shared__ int scnt[CN_], sbase[CN_];
    int t = threadIdx.x;
    if (t < CN_) scnt[t] = 0;
    __syncthreads();
    int r = blockIdx.x * 256 + t;
    int c = lab[r];
    int local = atomicAdd(&scnt[c], 1);
    __syncthreads();
    if (t < CN_) sbase[t] = atomicAdd(&g_cnt[t], scnt[t]);
    __syncthreads();
    g_idx[c * ROWS_ + sbase[c] + local] = r;
}

// ---------------- kernel 3: compact tile list ----------------
__global__ void k_tiles() {
    __shared__ int pfx[CN_ + 1];
    int t = threadIdx.x;
    if (t == 0) {
        int off = 0;
        for (int c = 0; c < CN_; c++) {
            pfx[c] = off;
            off += (g_cnt[c] + 127) >> 7;
        }
        pfx[CN_] = off;
        g_nt = off;
    }
    __syncthreads();
    int nt = pfx[CN_];
    for (int i = t; i < nt; i += blockDim.x) {
        int c = 0;
        while (c < CN_ - 1 && i >= pfx[c + 1]) c++;
        g_tile[i] = make_int2(c, (i - pfx[c]) << 7);
    }
}

// ---------------- kernel 4: pre-split weights to bf16 hi/lo ----------------
__global__ void k_prepB(const float* __restrict__ Wn) {
    int c = blockIdx.x;
    for (int i = threadIdx.x; i < DNEI_ * E_; i += blockDim.x) {
        float w = Wn[c * DNEI_ * E_ + i];
        __nv_bfloat16 h = __float2bfloat16(w);
        __nv_bfloat16 l = __float2bfloat16(w - __bfloat162float(h));
        g_Bhi[c * DNEI_ * E_ + i] = h;
        g_Blo[c * DNEI_ * E_ + i] = l;
    }
}

// ---------------- kernel 5: self embedding (float4) ----------------
__global__ void k_self(const float* __restrict__ obs,
                       const float* __restrict__ Ws,
                       const int*   __restrict__ lab,
                       float*       __restrict__ outx) {
    __shared__ float os[48];
    int b = blockIdx.x;
    int t = threadIdx.x;              // 0..127
    if (t < 12) ((float4*)os)[t] = ((const float4*)(obs + b * 48))[t];
    int c = lab[b];
    __syncthreads();
    const float* W = Ws + c * DSELF_ * E_ + t * 4;
    float4 acc = make_float4(0.f, 0.f, 0.f, 0.f);
#pragma unroll
    for (int j = 0; j < 48; j++) {
        float4 w = *(const float4*)(W + j * E_);
        float a = os[j];
        acc.x += a * w.x; acc.y += a * w.y; acc.z += a * w.z; acc.w += a * w.w;
    }
    const float4* ap = (const float4*)(g_anchor + c * K_ * E_) + t;
    float4* o = (float4*)(outx + b * K_ * E_) + t;
#pragma unroll
    for (int k = 0; k < K_; k++) {
        float4 an = ap[k * (E_ / 4)];
        o[k * (E_ / 4)] = make_float4(acc.x + an.x, acc.y + an.y, acc.z + an.z, acc.w + an.w);
    }
}

// ---------------- kernel 6: bf16x3 mma.sync GEMM ----------------
// smem (bytes):
//   A_hi [128][56] bf16 = 14336 @ 0
//   A_lo [128][56] bf16 = 14336 @ 14336
//   B_hi [48][136] bf16 = 13056 @ 28672
//   B_lo [48][136] bf16 = 13056 @ 41728
//   bias f32[128]       =   512 @ 54784   -> total 55296
#define ASTRIDE_B 112   /* 56 bf16 */
#define BSTRIDE_B 272   /* 136 bf16 */
#define SM_AHI 0
#define SM_ALO 14336
#define SM_BHI 28672
#define SM_BLO 41728
#define SM_BIAS 54784
#define SM_BYTES 55296

__global__ void __launch_bounds__(256, 2)
k_nei(const float* __restrict__ neis,
      const float* __restrict__ bn,
      float*       __restrict__ outn) {
    extern __shared__ char smem[];
    if (blockIdx.y >= g_nt) return;
    int2 tl  = g_tile[blockIdx.y];
    int c    = tl.x;
    int base = tl.y;
    int cnt  = g_cnt[c];
    int e0   = blockIdx.x << 7;
    int tid  = threadIdx.x;

    // bias
    if (tid < 128) ((float*)(smem + SM_BIAS))[tid] = bn[c * E_ + e0 + tid];

    // --- B tiles: copy pre-split bf16, pad k-row stride to 136 ---
#pragma unroll
    for (int p = 0; p < 12; p++) {
        int lin = p * 256 + tid;          // 0..3071 u32 (=2 bf16 each)
        int k   = lin >> 6;
        int n2  = lin & 63;
        uint32_t vh = ((const uint32_t*)(g_Bhi + (c * DNEI_ + k) * E_ + e0))[n2];
        uint32_t vl = ((const uint32_t*)(g_Blo + (c * DNEI_ + k) * E_ + e0))[n2];
        ((uint32_t*)(smem + SM_BHI + k * BSTRIDE_B))[n2] = vh;
        ((uint32_t*)(smem + SM_BLO + k * BSTRIDE_B))[n2] = vl;
    }

    // --- A tile: gather + srecip + bf16 split, row stride 56 ---
#pragma unroll
    for (int p = 0; p < 6; p++) {
        int lin = p * 256 + tid;          // 0..1535
        int row = lin / 12;
        int v   = lin - row * 12;         // float4 index within the 48-float row
        int gi  = base + row;
        float4 a = make_float4(0.f, 0.f, 0.f, 0.f);
        if (gi < cnt) {
            int rr = g_idx[c * ROWS_ + gi];
            a = ((const float4*)(neis + (long long)rr * 48))[v];
            a.x = srecip(a.x); a.y = srecip(a.y); a.z = srecip(a.z); a.w = srecip(a.w);
        }
        __nv_bfloat162 h0, h1, l0, l1;
        h0.x = __float2bfloat16(a.x); l0.x = __float2bfloat16(a.x - __bfloat162float(h0.x));
        h0.y = __float2bfloat16(a.y); l0.y = __float2bfloat16(a.y - __bfloat162float(h0.y));
        h1.x = __float2bfloat16(a.z); l1.x = __float2bfloat16(a.z - __bfloat162float(h1.x));
        h1.y = __float2bfloat16(a.w); l1.y = __float2bfloat16(a.w - __bfloat162float(h1.y));
        __nv_bfloat162* dh = (__nv_bfloat162*)(smem + SM_AHI + row * ASTRIDE_B);
        __nv_bfloat162* dl = (__nv_bfloat162*)(smem + SM_ALO + row * ASTRIDE_B);
        dh[v * 2] = h0; dh[v * 2 + 1] = h1;
        dl[v * 2] = l0; dl[v * 2 + 1] = l1;
    }
    __syncthreads();

    // --- compute: 8 warps = 2(m) x 4(n); warp tile 64x32 ---
    int w    = tid >> 5;
    int lane = tid & 31;
    int wm   = w >> 2;
    int wn   = w & 3;

    float acc[16][4];
#pragma unroll
    for (int i = 0; i < 16; i++) {
        acc[i][0] = 0.f; acc[i][1] = 0.f; acc[i][2] = 0.f; acc[i][3] = 0.f;
    }

    uint32_t sb = smem_u32(smem);
    // A ldmatrix lane address pieces
    int rowL = wm * 64 + ((lane >> 3) & 1) * 8 + (lane & 7);
    int kLa  = (lane >> 4) * 8;
    uint32_t aLane = sb + (uint32_t)(rowL * ASTRIDE_B + kLa * 2);
    // B ldmatrix (trans) lane address pieces
    int kLb = ((lane >> 3) & 1) * 8 + (lane & 7);
    int nLb = (lane >> 4) * 8;
    uint32_t bLane = sb + (uint32_t)(kLb * BSTRIDE_B + (wn * 32 + nLb) * 2);

#pragma unroll
    for (int pc = 0; pc < 3; pc++) {
        uint32_t aOff = (pc == 1) ? SM_ALO : SM_AHI;
        uint32_t bOff = (pc == 2) ? SM_BLO : SM_BHI;
#pragma unroll
        for (int ks = 0; ks < 3; ks++) {
            uint32_t af[4][4], bfr[2][4];
#pragma unroll
            for (int mi = 0; mi < 4; mi++)
                ldsm4(af[mi], aLane + aOff + mi * 16 * ASTRIDE_B + ks * 32);
#pragma unroll
            for (int ng = 0; ng < 2; ng++)
                ldsm4t(bfr[ng], bLane + bOff + ks * 16 * BSTRIDE_B + ng * 32);
#pragma unroll
            for (int mi = 0; mi < 4; mi++) {
#pragma unroll
                for (int ni = 0; ni < 4; ni++)
                    mma_bf16(acc[mi * 4 + ni], af[mi],
                             bfr[ni >> 1][(ni & 1) * 2], bfr[ni >> 1][(ni & 1) * 2 + 1]);
            }
        }
    }

    // --- epilogue: bias add + scatter rows ---
    const float* bias = (const float*)(smem + SM_BIAS) + wn * 32;
    int qr = lane >> 2;
    int qc = (lane & 3) * 2;
#pragma unroll
    for (int mi = 0; mi < 4; mi++) {
#pragma unroll
        for (int hf = 0; hf < 2; hf++) {
            int gi = base + wm * 64 + mi * 16 + hf * 8 + qr;
            if (gi < cnt) {
                int rg = g_idx[c * ROWS_ + gi];
                float* o = outn + (long long)rg * E_ + e0 + wn * 32 + qc;
#pragma unroll
                for (int ni = 0; ni < 4; ni++) {
                    float2 v;
                    v.x = acc[mi * 4 + ni][hf * 2 + 0] + bias[ni * 8 + qc];
                    v.y = acc[mi * 4 + ni][hf * 2 + 1] + bias[ni * 8 + qc + 1];
                    *(float2*)(o + ni * 8) = v;
                }
            }
        }
    }
}

// ---------------- launch ----------------
extern "C" void kernel_launch(void* const* d_in, const int* in_sizes, int n_in,
                              void* d_out, int out_size) {
    const float* obs  = (const float*)d_in[0];
    const float* neis = (const float*)d_in[1];
    const float* it   = (const float*)d_in[2];
    const float* Ws   = (const float*)d_in[3];
    const float* bs   = (const float*)d_in[4];
    const float* Wn   = (const float*)d_in[5];
    const float* bn   = (const float*)d_in[6];
    const int*   slab = (const int*)d_in[7];
    const int*   nlab = (const int*)d_in[8];

    float* outx = (float*)d_out;            // [B, K, E]
    float* outn = outx + XSIZE_;            // [B, N, E]

    cudaFuncSetAttribute(k_nei, cudaFuncAttributeMaxDynamicSharedMemorySize, SM_BYTES);

    k_anchor<<<C_ * K_, 512>>>(it, Ws, bs);
    k_bucket<<<ROWS_ / 256, 256>>>(nlab);
    k_tiles<<<1, 128>>>();
    k_prepB<<<CN_, 256>>>(Wn);
    k_self<<<B_, 128>>>(obs, Ws, slab, outx);
    dim3 g(4, MAXTILES_, 1);
    k_nei<<<g, 256, SM_BYTES>>>(neis, bn, outn);
}

// round 4
// speedup vs baseline: 1.1971x; 1.1971x over previous
#include <cuda_runtime.h>
#include <cuda_fp16.h>
#include <cstdint>

#define EPS_ 1e-4f

#define B_     2048
#define N_     64
#define E_     512
#define C_     6
#define CN_    7
#define K_     20
#define DSELF_ 120
#define DNEI_  48
#define ROWS_  (B_ * N_)        /* 131072 */
#define XSIZE_ (B_ * K_ * E_)   /* 20971520 */

#define MAXTILES_ 1032

// ---------------- device scratch (no allocations allowed) ----------------
__device__ float g_anchor[C_ * K_ * E_];     // [c,k,e]
__device__ int   g_cnt[CN_];
__device__ int   g_idx[CN_ * ROWS_];
__device__ int   g_nt;
__device__ int2  g_tile[MAXTILES_];          // (class, base)
__device__ __half g_Bh[CN_ * DNEI_ * E_];    // fp16 weights [c][k][e]

// ---------------- helpers ----------------
__device__ __forceinline__ uint32_t smem_u32(const void* p) {
    uint32_t a;
    asm("{ .reg .u64 t; cvta.to.shared.u64 t, %1; cvt.u32.u64 %0, t; }" : "=r"(a) : "l"(p));
    return a;
}
__device__ __forceinline__ float srecip(float x) {
    float d = x + (x >= 0.0f ? EPS_ : -EPS_);
    return __fdividef(1.0f, d);
}
__device__ __forceinline__ void ldsm4(uint32_t (&r)[4], uint32_t addr) {
    asm volatile("ldmatrix.sync.aligned.m8n8.x4.shared.b16 {%0,%1,%2,%3}, [%4];"
                 : "=r"(r[0]), "=r"(r[1]), "=r"(r[2]), "=r"(r[3]) : "r"(addr));
}
__device__ __forceinline__ void ldsm4t(uint32_t (&r)[4], uint32_t addr) {
    asm volatile("ldmatrix.sync.aligned.m8n8.x4.trans.shared.b16 {%0,%1,%2,%3}, [%4];"
                 : "=r"(r[0]), "=r"(r[1]), "=r"(r[2]), "=r"(r[3]) : "r"(addr));
}
__device__ __forceinline__ void mma_f16(float (&d)[4], const uint32_t (&a)[4],
                                        uint32_t b0, uint32_t b1) {
    asm volatile("mma.sync.aligned.m16n8k16.row.col.f32.f16.f16.f32 "
                 "{%0,%1,%2,%3}, {%4,%5,%6,%7}, {%8,%9}, {%0,%1,%2,%3};"
                 : "+f"(d[0]), "+f"(d[1]), "+f"(d[2]), "+f"(d[3])
                 : "r"(a[0]), "r"(a[1]), "r"(a[2]), "r"(a[3]), "r"(b0), "r"(b1));
}

// ---------------- L1: anchors + weight fp16 convert + counter zero ----------------
__global__ void k_pre(const float* __restrict__ it,
                      const float* __restrict__ Ws,
                      const float* __restrict__ bs,
                      const float* __restrict__ Wn) {
    int blk = blockIdx.x;
    int t   = threadIdx.x;
    if (blk < C_ * K_) {
        // anchor[c,k,e] = it[c,k]·W_self[c,48:120,e] + b_self[c,e]
        if (blk == 0 && t < CN_) g_cnt[t] = 0;
        __shared__ float its[72];
        int ck = blk;
        int c  = ck / K_;
        if (t < 18) ((float4*)its)[t] = ((const float4*)(it + ck * 72))[t];
        __syncthreads();
#pragma unroll
        for (int h = 0; h < 2; h++) {
            int e = t + h * 256;
            const float* W = Ws + c * DSELF_ * E_ + 48 * E_ + e;
            float a0 = 0.f, a1 = 0.f, a2 = 0.f, a3 = 0.f;
#pragma unroll
            for (int j = 0; j < 72; j += 4) {
                a0 += its[j + 0] * W[(j + 0) * E_];
                a1 += its[j + 1] * W[(j + 1) * E_];
                a2 += its[j + 2] * W[(j + 2) * E_];
                a3 += its[j + 3] * W[(j + 3) * E_];
            }
            g_anchor[ck * E_ + e] = (a0 + a1) + (a2 + a3) + bs[c * E_ + e];
        }
    } else {
        // W_nei -> fp16: 56 blocks = 7 classes x 8 slices of 3072 elems
        int pb = blk - C_ * K_;
        int c  = pb >> 3;
        int s  = pb & 7;
        const float* src = Wn + c * DNEI_ * E_;
        __half* dst = g_Bh + c * DNEI_ * E_;
        int base = s * 3072;
#pragma unroll
        for (int q = 0; q < 12; q++) {
            int i = base + q * 256 + t;
            dst[i] = __float2half_rn(src[i]);
        }
    }
}

// ---------------- L2: bucket rows by neighbor label ----------------
__global__ void k_bucket(const int* __restrict__ lab) {
    __shared__ int scnt[CN_], sbase[CN_];
    int t = threadIdx.x;
    if (t < CN_) scnt[t] = 0;
    __syncthreads();
    int r = blockIdx.x * 256 + t;
    int c = lab[r];
    int local = atomicAdd(&scnt[c], 1);
    __syncthreads();
    if (t < CN_) sbase[t] = atomicAdd(&g_cnt[t], scnt[t]);
    __syncthreads();
    g_idx[c * ROWS_ + sbase[c] + local] = r;
}

// ---------------- L3: compact tile list (block 0) + self embedding ----------------
__global__ void k_ts(const float* __restrict__ obs,
                     const float* __restrict__ Ws,
                     const int*   __restrict__ lab,
                     float*       __restrict__ outx) {
    if (blockIdx.x == 0) {
        __shared__ int pfx[CN_ + 1];
        int t = threadIdx.x;
        if (t == 0) {
            int off = 0;
            for (int c = 0; c < CN_; c++) {
                pfx[c] = off;
                off += (g_cnt[c] + 127) >> 7;
            }
            pfx[CN_] = off;
            g_nt = off;
        }
        __syncthreads();
        int nt = pfx[CN_];
        for (int i = t; i < nt; i += blockDim.x) {
            int c = 0;
            while (c < CN_ - 1 && i >= pfx[c + 1]) c++;
            g_tile[i] = make_int2(c, (i - pfx[c]) << 7);
        }
        return;
    }
    __shared__ float os[2][48];
    int sub = threadIdx.x >> 7;        // which of the 2 batch rows
    int tl  = threadIdx.x & 127;       // e-chunk (float4)
    int b   = (blockIdx.x - 1) * 2 + sub;
    if (tl < 12) ((float4*)os[sub])[tl] = ((const float4*)(obs + b * 48))[tl];
    int c = lab[b];
    __syncthreads();
    const float* W = Ws + c * DSELF_ * E_ + tl * 4;
    float4 acc = make_float4(0.f, 0.f, 0.f, 0.f);
#pragma unroll
    for (int j = 0; j < 48; j++) {
        float4 w = *(const float4*)(W + j * E_);
        float a = os[sub][j];
        acc.x += a * w.x; acc.y += a * w.y; acc.z += a * w.z; acc.w += a * w.w;
    }
    const float4* ap = (const float4*)(g_anchor + c * K_ * E_) + tl;
    float4* o = (float4*)(outx + b * K_ * E_) + tl;
#pragma unroll
    for (int k = 0; k < K_; k++) {
        float4 an = ap[k * (E_ / 4)];
        o[k * (E_ / 4)] = make_float4(acc.x + an.x, acc.y + an.y, acc.z + an.z, acc.w + an.w);
    }
}

// ---------------- L4: fp16 2-term mma.sync GEMM ----------------
// A' = [ah | al] : 128 rows x 96 k (fp16), row stride 104 halves (208 B, conflict-free)
// B  = bh       : 48 k x 128 n (fp16), k stride 136 halves (272 B, conflict-free)
// acc = ah*bh + al*bh  (exact A, fp16-rounded B)
#define ASTR_H 104
#define BSTR_H 136

__global__ void __launch_bounds__(256, 2)
k_nei(const float* __restrict__ neis,
      const float* __restrict__ bn,
      float*       __restrict__ outn) {
    __shared__ __half Ash[128 * ASTR_H];   // 26624 B
    __shared__ __half Bsh[48 * BSTR_H];    // 13056 B
    __shared__ float  bias[128];

    if (blockIdx.y >= g_nt) return;
    int2 tl  = g_tile[blockIdx.y];
    int c    = tl.x;
    int base = tl.y;
    int cnt  = g_cnt[c];
    int e0   = blockIdx.x << 7;
    int tid  = threadIdx.x;

    if (tid < 128) bias[tid] = bn[c * E_ + e0 + tid];

    // --- B tile: copy fp16 weights (48 x 128 halves = 3072 u32) ---
#pragma unroll
    for (int p = 0; p < 12; p++) {
        int lin = p * 256 + tid;
        int k   = lin >> 6;
        int n2  = lin & 63;
        ((uint32_t*)(Bsh + k * BSTR_H))[n2] =
            ((const uint32_t*)(g_Bh + (c * DNEI_ + k) * E_ + e0))[n2];
    }

    // --- A tile: gather + srecip + fp16 hi/lo split ---
#pragma unroll
    for (int p = 0; p < 6; p++) {
        int lin = p * 256 + tid;          // 0..1535
        int row = lin / 12;
        int v   = lin - row * 12;         // float4 index in the 48-float row
        int gi  = base + row;
        float4 a = make_float4(0.f, 0.f, 0.f, 0.f);
        if (gi < cnt) {
            int rr = g_idx[c * ROWS_ + gi];
            a = ((const float4*)(neis + (long long)rr * 48))[v];
            a.x = srecip(a.x); a.y = srecip(a.y); a.z = srecip(a.z); a.w = srecip(a.w);
        }
        __half hx = __float2half_rn(a.x), hy = __float2half_rn(a.y);
        __half hz = __float2half_rn(a.z), hw = __float2half_rn(a.w);
        __half lx = __float2half_rn(a.x - __half2float(hx));
        __half ly = __float2half_rn(a.y - __half2float(hy));
        __half lz = __float2half_rn(a.z - __half2float(hz));
        __half lw = __float2half_rn(a.w - __half2float(hw));
        __half2* dst = (__half2*)(Ash + row * ASTR_H + v * 4);
        dst[0] = __halves2half2(hx, hy);
        dst[1] = __halves2half2(hz, hw);
        __half2* dstl = (__half2*)(Ash + row * ASTR_H + 48 + v * 4);
        dstl[0] = __halves2half2(lx, ly);
        dstl[1] = __halves2half2(lz, lw);
    }
    __syncthreads();

    // --- compute: 8 warps = 2(m) x 4(n); warp tile 64x32 ---
    int w    = tid >> 5;
    int lane = tid & 31;
    int wm   = w >> 2;
    int wn   = w & 3;

    float acc[16][4];
#pragma unroll
    for (int i = 0; i < 16; i++) {
        acc[i][0] = 0.f; acc[i][1] = 0.f; acc[i][2] = 0.f; acc[i][3] = 0.f;
    }

    uint32_t sbA = smem_u32(Ash);
    uint32_t sbB = smem_u32(Bsh);
    int rowL = wm * 64 + ((lane >> 3) & 1) * 8 + (lane & 7);
    int kLa  = (lane >> 4) * 8;                       // halves
    uint32_t aLane = sbA + (uint32_t)(rowL * (ASTR_H * 2) + kLa * 2);
    int kLb = ((lane >> 3) & 1) * 8 + (lane & 7);
    int nLb = (lane >> 4) * 8;
    uint32_t bLane = sbB + (uint32_t)(kLb * (BSTR_H * 2) + (wn * 32 + nLb) * 2);

#pragma unroll
    for (int ks = 0; ks < 6; ks++) {
        int kb = (ks < 3) ? ks : (ks - 3);            // B reused for lo half
        uint32_t af[4][4], bfr[2][4];
#pragma unroll
        for (int mi = 0; mi < 4; mi++)
            ldsm4(af[mi], aLane + mi * 16 * (ASTR_H * 2) + ks * 32);
#pragma unroll
        for (int ng = 0; ng < 2; ng++)
            ldsm4t(bfr[ng], bLane + kb * 16 * (BSTR_H * 2) + ng * 32);
#pragma unroll
        for (int mi = 0; mi < 4; mi++) {
#pragma unroll
            for (int ni = 0; ni < 4; ni++)
                mma_f16(acc[mi * 4 + ni], af[mi],
                        bfr[ni >> 1][(ni & 1) * 2], bfr[ni >> 1][(ni & 1) * 2 + 1]);
        }
    }

    // --- epilogue: bias add + scatter rows ---
    const float* bp = bias + wn * 32;
    int qr = lane >> 2;
    int qc = (lane & 3) * 2;
#pragma unroll
    for (int mi = 0; mi < 4; mi++) {
#pragma unroll
        for (int hf = 0; hf < 2; hf++) {
            int gi = base + wm * 64 + mi * 16 + hf * 8 + qr;
            if (gi < cnt) {
                int rg = g_idx[c * ROWS_ + gi];
                float* o = outn + (long long)rg * E_ + e0 + wn * 32 + qc;
#pragma unroll
                for (int ni = 0; ni < 4; ni++) {
                    float2 v;
                    v.x = acc[mi * 4 + ni][hf * 2 + 0] + bp[ni * 8 + qc];
                    v.y = acc[mi * 4 + ni][hf * 2 + 1] + bp[ni * 8 + qc + 1];
                    *(float2*)(o + ni * 8) = v;
                }
            }
        }
    }
}

// ---------------- launch ----------------
extern "C" void kernel_launch(void* const* d_in, const int* in_sizes, int n_in,
                              void* d_out, int out_size) {
    const float* obs  = (const float*)d_in[0];
    const float* neis = (const float*)d_in[1];
    const float* it   = (const float*)d_in[2];
    const float* Ws   = (const float*)d_in[3];
    const float* bs   = (const float*)d_in[4];
    const float* Wn   = (const float*)d_in[5];
    const float* bn   = (const float*)d_in[6];
    const int*   slab = (const int*)d_in[7];
    const int*   nlab = (const int*)d_in[8];

    float* outx = (float*)d_out;            // [B, K, E]
    float* outn = outx + XSIZE_;            // [B, N, E]

    k_pre<<<C_ * K_ + CN_ * 8, 256>>>(it, Ws, bs, Wn);
    k_bucket<<<ROWS_ / 256, 256>>>(nlab);
    k_ts<<<1 + B_ / 2, 256>>>(obs, Ws, slab, outx);
    dim3 g(4, MAXTILES_, 1);
    k_nei<<<g, 256>>>(neis, bn, outn);
}

// round 5
// speedup vs baseline: 1.8236x; 1.5234x over previous
#include <cuda_runtime.h>
#include <cuda_fp16.h>
#include <cstdint>

#define EPS_ 1e-4f

#define B_     2048
#define N_     64
#define E_     512
#define C_     6
#define CN_    7
#define K_     20
#define DSELF_ 120
#define DNEI_  48
#define ROWS_  (B_ * N_)        /* 131072 */
#define XSIZE_ (B_ * K_ * E_)   /* 20971520 */

#define MAXTILES_ 1032

// ---------------- device scratch ----------------
__device__ float g_anchor[C_ * K_ * E_];
__device__ int   g_cnt[CN_];
__device__ int   g_idx[CN_ * ROWS_];
__device__ int   g_nt;
__device__ int2  g_tile[MAXTILES_];
__device__ __half g_Bh[CN_ * DNEI_ * E_];    // fp16 weights [c][k][e]

// ---------------- helpers ----------------
__device__ __forceinline__ uint32_t smem_u32(const void* p) {
    uint32_t a;
    asm("{ .reg .u64 t; cvta.to.shared.u64 t, %1; cvt.u32.u64 %0, t; }" : "=r"(a) : "l"(p));
    return a;
}
__device__ __forceinline__ float srecip(float x) {
    float d = x + (x >= 0.0f ? EPS_ : -EPS_);
    return __fdividef(1.0f, d);
}
__device__ __forceinline__ void ldsm4(uint32_t (&r)[4], uint32_t addr) {
    asm volatile("ldmatrix.sync.aligned.m8n8.x4.shared.b16 {%0,%1,%2,%3}, [%4];"
                 : "=r"(r[0]), "=r"(r[1]), "=r"(r[2]), "=r"(r[3]) : "r"(addr));
}
__device__ __forceinline__ void ldsm4t(uint32_t (&r)[4], uint32_t addr) {
    asm volatile("ldmatrix.sync.aligned.m8n8.x4.trans.shared.b16 {%0,%1,%2,%3}, [%4];"
                 : "=r"(r[0]), "=r"(r[1]), "=r"(r[2]), "=r"(r[3]) : "r"(addr));
}
__device__ __forceinline__ void mma_f16(float (&d)[4], const uint32_t (&a)[4],
                                        uint32_t b0, uint32_t b1) {
    asm volatile("mma.sync.aligned.m16n8k16.row.col.f32.f16.f16.f32 "
                 "{%0,%1,%2,%3}, {%4,%5,%6,%7}, {%8,%9}, {%0,%1,%2,%3};"
                 : "+f"(d[0]), "+f"(d[1]), "+f"(d[2]), "+f"(d[3])
                 : "r"(a[0]), "r"(a[1]), "r"(a[2]), "r"(a[3]), "r"(b0), "r"(b1));
}
__device__ __forceinline__ void cpa16(uint32_t dst, const void* src) {
    asm volatile("cp.async.cg.shared.global [%0], [%1], 16;" :: "r"(dst), "l"(src) : "memory");
}
#define CPA_COMMIT() asm volatile("cp.async.commit_group;" ::: "memory")
#define CPA_WAIT0()  asm volatile("cp.async.wait_group 0;" ::: "memory")

// ---------------- L1: anchors + weight fp16 convert + counter zero ----------------
__global__ void k_pre(const float* __restrict__ it,
                      const float* __restrict__ Ws,
                      const float* __restrict__ bs,
                      const float* __restrict__ Wn) {
    int blk = blockIdx.x;
    int t   = threadIdx.x;
    if (blk < C_ * K_) {
        if (blk == 0 && t < CN_) g_cnt[t] = 0;
        __shared__ float its[72];
        int ck = blk;
        int c  = ck / K_;
        if (t < 18) ((float4*)its)[t] = ((const float4*)(it + ck * 72))[t];
        __syncthreads();
#pragma unroll
        for (int h = 0; h < 2; h++) {
            int e = t + h * 256;
            const float* W = Ws + c * DSELF_ * E_ + 48 * E_ + e;
            float a0 = 0.f, a1 = 0.f, a2 = 0.f, a3 = 0.f;
#pragma unroll
            for (int j = 0; j < 72; j += 4) {
                a0 += its[j + 0] * W[(j + 0) * E_];
                a1 += its[j + 1] * W[(j + 1) * E_];
                a2 += its[j + 2] * W[(j + 2) * E_];
                a3 += its[j + 3] * W[(j + 3) * E_];
            }
            g_anchor[ck * E_ + e] = (a0 + a1) + (a2 + a3) + bs[c * E_ + e];
        }
    } else {
        int pb = blk - C_ * K_;
        int c  = pb >> 3;
        int s  = pb & 7;
        const float* src = Wn + c * DNEI_ * E_;
        __half* dst = g_Bh + c * DNEI_ * E_;
        int base = s * 3072;
#pragma unroll
        for (int q = 0; q < 12; q++) {
            int i = base + q * 256 + t;
            dst[i] = __float2half_rn(src[i]);
        }
    }
}

// ---------------- L2: bucket rows by neighbor label ----------------
__global__ void k_bucket(const int* __restrict__ lab) {
    __shared__ int scnt[CN_], sbase[CN_];
    int t = threadIdx.x;
    if (t < CN_) scnt[t] = 0;
    __syncthreads();
    int r = blockIdx.x * 256 + t;
    int c = lab[r];
    int local = atomicAdd(&scnt[c], 1);
    __syncthreads();
    if (t < CN_) sbase[t] = atomicAdd(&g_cnt[t], scnt[t]);
    __syncthreads();
    g_idx[c * ROWS_ + sbase[c] + local] = r;
}

// ---------------- L3: compact tile list (block 0) + self embedding ----------------
__global__ void k_ts(const float* __restrict__ obs,
                     const float* __restrict__ Ws,
                     const int*   __restrict__ lab,
                     float*       __restrict__ outx) {
    if (blockIdx.x == 0) {
        __shared__ int pfx[CN_ + 1];
        int t = threadIdx.x;
        if (t == 0) {
            int off = 0;
            for (int c = 0; c < CN_; c++) {
                pfx[c] = off;
                off += (g_cnt[c] + 127) >> 7;
            }
            pfx[CN_] = off;
            g_nt = off;
        }
        __syncthreads();
        int nt = pfx[CN_];
        for (int i = t; i < nt; i += blockDim.x) {
            int c = 0;
            while (c < CN_ - 1 && i >= pfx[c + 1]) c++;
            g_tile[i] = make_int2(c, (i - pfx[c]) << 7);
        }
        return;
    }
    __shared__ float os[2][48];
    int sub = threadIdx.x >> 7;
    int tl  = threadIdx.x & 127;
    int b   = (blockIdx.x - 1) * 2 + sub;
    if (tl < 12) ((float4*)os[sub])[tl] = ((const float4*)(obs + b * 48))[tl];
    int c = lab[b];
    __syncthreads();
    const float* W = Ws + c * DSELF_ * E_ + tl * 4;
    float4 acc = make_float4(0.f, 0.f, 0.f, 0.f);
#pragma unroll
    for (int j = 0; j < 48; j++) {
        float4 w = *(const float4*)(W + j * E_);
        float a = os[sub][j];
        acc.x += a * w.x; acc.y += a * w.y; acc.z += a * w.z; acc.w += a * w.w;
    }
    const float4* ap = (const float4*)(g_anchor + c * K_ * E_) + tl;
    float4* o = (float4*)(outx + b * K_ * E_) + tl;
#pragma unroll
    for (int k = 0; k < K_; k++) {
        float4 an = ap[k * (E_ / 4)];
        o[k * (E_ / 4)] = make_float4(acc.x + an.x, acc.y + an.y, acc.z + an.z, acc.w + an.w);
    }
}

// ---------------- L4: fp16 2-term GEMM, A reused over 4 e-chunks, B double-buffered ----------------
// dyn smem: A' [128 x 104 halves] @ 0          (26624 B)
//           B[2][48 x 136 halves] @ 26624      (2 x 13056 B)   total 52736 B
#define ASTR_H 104
#define BSTR_H 136
#define SM_A   0
#define SM_B   26624
#define BBUF_B 13056
#define SM_BYTES 52736

__global__ void __launch_bounds__(256, 2)
k_nei(const float* __restrict__ neis,
      const float* __restrict__ bn,
      float*       __restrict__ outn) {
    extern __shared__ char smem[];
    if (blockIdx.x >= g_nt) return;
    int2 tl  = g_tile[blockIdx.x];
    int c    = tl.x;
    int base = tl.y;
    int cnt  = g_cnt[c];
    int tid  = threadIdx.x;

    uint32_t sb = smem_u32(smem);

    // --- prefetch B[0] (et=0) via cp.async ---
    {
        const __half* gb = g_Bh + c * DNEI_ * E_;   // e0 = 0
#pragma unroll
        for (int p = 0; p < 3; p++) {
            int chunk = p * 256 + tid;              // 0..767
            int k  = chunk >> 4;
            int cc = chunk & 15;
            cpa16(sb + SM_B + k * (BSTR_H * 2) + cc * 16,
                  gb + k * E_ + cc * 8);
        }
        CPA_COMMIT();
    }

    // --- A tile: gather + srecip + fp16 hi/lo split (once) ---
#pragma unroll
    for (int p = 0; p < 6; p++) {
        int lin = p * 256 + tid;
        int row = lin / 12;
        int v   = lin - row * 12;
        int gi  = base + row;
        float4 a = make_float4(0.f, 0.f, 0.f, 0.f);
        if (gi < cnt) {
            int rr = g_idx[c * ROWS_ + gi];
            a = ((const float4*)(neis + (long long)rr * 48))[v];
            a.x = srecip(a.x); a.y = srecip(a.y); a.z = srecip(a.z); a.w = srecip(a.w);
        }
        __half hx = __float2half_rn(a.x), hy = __float2half_rn(a.y);
        __half hz = __float2half_rn(a.z), hw = __float2half_rn(a.w);
        __half lx = __float2half_rn(a.x - __half2float(hx));
        __half ly = __float2half_rn(a.y - __half2float(hy));
        __half lz = __float2half_rn(a.z - __half2float(hz));
        __half lw = __float2half_rn(a.w - __half2float(hw));
        __half2* dst = (__half2*)(smem + SM_A + row * (ASTR_H * 2) + v * 8);
        dst[0] = __halves2half2(hx, hy);
        dst[1] = __halves2half2(hz, hw);
        __half2* dstl = (__half2*)(smem + SM_A + row * (ASTR_H * 2) + 96 + v * 8);
        dstl[0] = __halves2half2(lx, ly);
        dstl[1] = __halves2half2(lz, lw);
    }

    // --- lane mapping ---
    int w    = tid >> 5;
    int lane = tid & 31;
    int wm   = w >> 2;
    int wn   = w & 3;

    int rowL = wm * 64 + ((lane >> 3) & 1) * 8 + (lane & 7);
    int kLa  = (lane >> 4) * 8;
    uint32_t aLane = sb + SM_A + (uint32_t)(rowL * (ASTR_H * 2) + kLa * 2);
    int kLb = ((lane >> 3) & 1) * 8 + (lane & 7);
    int nLb = (lane >> 4) * 8;
    uint32_t bLaneBase = sb + SM_B + (uint32_t)(kLb * (BSTR_H * 2) + (wn * 32 + nLb) * 2);

    // epilogue row indices (fixed across et)
    int qr = lane >> 2;
    int qc = (lane & 3) * 2;
    int rg_[8];
    bool val_[8];
#pragma unroll
    for (int mi = 0; mi < 4; mi++) {
#pragma unroll
        for (int hf = 0; hf < 2; hf++) {
            int gi = base + wm * 64 + mi * 16 + hf * 8 + qr;
            val_[mi * 2 + hf] = gi < cnt;
            rg_[mi * 2 + hf]  = (gi < cnt) ? g_idx[c * ROWS_ + gi] : 0;
        }
    }

    // --- loop over 4 e-chunks ---
#pragma unroll
    for (int et = 0; et < 4; et++) {
        CPA_WAIT0();                 // B[et] arrived
        __syncthreads();             // visible to all; prev compute done -> other buf free

        // prefetch B[et+1] into the other buffer
        if (et < 3) {
            const __half* gb = g_Bh + c * DNEI_ * E_ + (et + 1) * 128;
            uint32_t dstb = sb + SM_B + ((et + 1) & 1) * BBUF_B;
#pragma unroll
            for (int p = 0; p < 3; p++) {
                int chunk = p * 256 + tid;
                int k  = chunk >> 4;
                int cc = chunk & 15;
                cpa16(dstb + k * (BSTR_H * 2) + cc * 16,
                      gb + k * E_ + cc * 8);
            }
            CPA_COMMIT();
        }

        float acc[16][4];
#pragma unroll
        for (int i = 0; i < 16; i++) {
            acc[i][0] = 0.f; acc[i][1] = 0.f; acc[i][2] = 0.f; acc[i][3] = 0.f;
        }

        uint32_t bLane = bLaneBase + (et & 1) * BBUF_B;
#pragma unroll
        for (int ks = 0; ks < 6; ks++) {
            int kb = (ks < 3) ? ks : (ks - 3);
            uint32_t af[4][4], bfr[2][4];
#pragma unroll
            for (int mi = 0; mi < 4; mi++)
                ldsm4(af[mi], aLane + mi * 16 * (ASTR_H * 2) + ks * 32);
#pragma unroll
            for (int ng = 0; ng < 2; ng++)
                ldsm4t(bfr[ng], bLane + kb * 16 * (BSTR_H * 2) + ng * 32);
#pragma unroll
            for (int mi = 0; mi < 4; mi++) {
#pragma unroll
                for (int ni = 0; ni < 4; ni++)
                    mma_f16(acc[mi * 4 + ni], af[mi],
                            bfr[ni >> 1][(ni & 1) * 2], bfr[ni >> 1][(ni & 1) * 2 + 1]);
            }
        }

        // epilogue: bias (global, cached) + scatter
        int e0 = et << 7;
        const float* bp = bn + c * E_ + e0 + wn * 32 + qc;
        float bx[4], by[4];
#pragma unroll
        for (int ni = 0; ni < 4; ni++) { bx[ni] = bp[ni * 8]; by[ni] = bp[ni * 8 + 1]; }
#pragma unroll
        for (int mi = 0; mi < 4; mi++) {
#pragma unroll
            for (int hf = 0; hf < 2; hf++) {
                if (val_[mi * 2 + hf]) {
                    float* o = outn + (long long)rg_[mi * 2 + hf] * E_ + e0 + wn * 32 + qc;
#pragma unroll
                    for (int ni = 0; ni < 4; ni++) {
                        float2 v;
                        v.x = acc[mi * 4 + ni][hf * 2 + 0] + bx[ni];
                        v.y = acc[mi * 4 + ni][hf * 2 + 1] + by[ni];
                        *(float2*)(o + ni * 8) = v;
                    }
                }
            }
        }
    }
}

// ---------------- launch ----------------
extern "C" void kernel_launch(void* const* d_in, const int* in_sizes, int n_in,
                              void* d_out, int out_size) {
    const float* obs  = (const float*)d_in[0];
    const float* neis = (const float*)d_in[1];
    const float* it   = (const float*)d_in[2];
    const float* Ws   = (const float*)d_in[3];
    const float* bs   = (const float*)d_in[4];
    const float* Wn   = (const float*)d_in[5];
    const float* bn   = (const float*)d_in[6];
    const int*   slab = (const int*)d_in[7];
    const int*   nlab = (const int*)d_in[8];

    float* outx = (float*)d_out;            // [B, K, E]
    float* outn = outx + XSIZE_;            // [B, N, E]

    cudaFuncSetAttribute(k_nei, cudaFuncAttributeMaxDynamicSharedMemorySize, SM_BYTES);

    k_pre<<<C_ * K_ + CN_ * 8, 256>>>(it, Ws, bs, Wn);
    k_bucket<<<ROWS_ / 256, 256>>>(nlab);
    k_ts<<<1 + B_ / 2, 256>>>(obs, Ws, slab, outx);
    k_nei<<<MAXTILES_, 256, SM_BYTES>>>(neis, bn, outn);
}

// round 8
// speedup vs baseline: 1.9080x; 1.0463x over previous
#include <cuda_runtime.h>
#include <cuda_fp16.h>
#include <cstdint>

#define EPS_ 1e-4f

#define B_     2048
#define N_     64
#define E_     512
#define C_     6
#define CN_    7
#define K_     20
#define DSELF_ 120
#define DNEI_  48
#define ROWS_  (B_ * N_)        /* 131072 */
#define XSIZE_ (B_ * K_ * E_)   /* 20971520 */

#define TILE_M 64
#define NEI_B  2056             /* >= sum ceil(cnt_c/64) = 2048+6 */

// ---------------- device scratch ----------------
__device__ float g_anchor[C_ * K_ * E_];
__device__ int   g_cnt[CN_];
__device__ int   g_idx[CN_ * ROWS_];
__device__ int   g_nt;
__device__ int   g_done;
__device__ int2  g_tile[NEI_B];
__device__ __half g_Bh[CN_ * DNEI_ * E_];    // fp16 weights [c][k][e]

// ---------------- helpers ----------------
__device__ __forceinline__ uint32_t smem_u32(const void* p) {
    uint32_t a;
    asm("{ .reg .u64 t; cvta.to.shared.u64 t, %1; cvt.u32.u64 %0, t; }" : "=r"(a) : "l"(p));
    return a;
}
__device__ __forceinline__ float srecip(float x) {
    float d = x + (x >= 0.0f ? EPS_ : -EPS_);
    return __fdividef(1.0f, d);
}
__device__ __forceinline__ void ldsm4(uint32_t (&r)[4], uint32_t addr) {
    asm volatile("ldmatrix.sync.aligned.m8n8.x4.shared.b16 {%0,%1,%2,%3}, [%4];"
                 : "=r"(r[0]), "=r"(r[1]), "=r"(r[2]), "=r"(r[3]) : "r"(addr));
}
__device__ __forceinline__ void ldsm4t(uint32_t (&r)[4], uint32_t addr) {
    asm volatile("ldmatrix.sync.aligned.m8n8.x4.trans.shared.b16 {%0,%1,%2,%3}, [%4];"
                 : "=r"(r[0]), "=r"(r[1]), "=r"(r[2]), "=r"(r[3]) : "r"(addr));
}
__device__ __forceinline__ void mma_f16(float (&d)[4], const uint32_t (&a)[4],
                                        uint32_t b0, uint32_t b1) {
    asm volatile("mma.sync.aligned.m16n8k16.row.col.f32.f16.f16.f32 "
                 "{%0,%1,%2,%3}, {%4,%5,%6,%7}, {%8,%9}, {%0,%1,%2,%3};"
                 : "+f"(d[0]), "+f"(d[1]), "+f"(d[2]), "+f"(d[3])
                 : "r"(a[0]), "r"(a[1]), "r"(a[2]), "r"(a[3]), "r"(b0), "r"(b1));
}
__device__ __forceinline__ void cpa16(uint32_t dst, const void* src) {
    asm volatile("cp.async.cg.shared.global [%0], [%1], 16;" :: "r"(dst), "l"(src) : "memory");
}
#define CPA_COMMIT() asm volatile("cp.async.commit_group;" ::: "memory")
#define CPA_WAIT0()  asm volatile("cp.async.wait_group 0;" ::: "memory")

// ---------------- L1: anchors + weight fp16 convert + zero flags ----------------
__global__ void k_pre(const float* __restrict__ it,
                      const float* __restrict__ Ws,
                      const float* __restrict__ bs,
                      const float* __restrict__ Wn) {
    int blk = blockIdx.x;
    int t   = threadIdx.x;
    if (blk < C_ * K_) {
        if (blk == 0 && t < CN_) g_cnt[t] = 0;
        if (blk == 0 && t == CN_) g_done = 0;
        __shared__ float its[72];
        int ck = blk;
        int c  = ck / K_;
        if (t < 18) ((float4*)its)[t] = ((const float4*)(it + ck * 72))[t];
        __syncthreads();
#pragma unroll
        for (int h = 0; h < 2; h++) {
            int e = t + h * 256;
            const float* W = Ws + c * DSELF_ * E_ + 48 * E_ + e;
            float a0 = 0.f, a1 = 0.f, a2 = 0.f, a3 = 0.f;
#pragma unroll
            for (int j = 0; j < 72; j += 4) {
                a0 += its[j + 0] * W[(j + 0) * E_];
                a1 += its[j + 1] * W[(j + 1) * E_];
                a2 += its[j + 2] * W[(j + 2) * E_];
                a3 += its[j + 3] * W[(j + 3) * E_];
            }
            g_anchor[ck * E_ + e] = (a0 + a1) + (a2 + a3) + bs[c * E_ + e];
        }
    } else {
        int pb = blk - C_ * K_;
        int c  = pb >> 3;
        int s  = pb & 7;
        const float* src = Wn + c * DNEI_ * E_;
        __half* dst = g_Bh + c * DNEI_ * E_;
        int base = s * 3072;
#pragma unroll
        for (int q = 0; q < 12; q++) {
            int i = base + q * 256 + t;
            dst[i] = __float2half_rn(src[i]);
        }
    }
}

// ---------------- L2: bucket rows + last block builds tile list ----------------
__global__ void k_bucket(const int* __restrict__ lab) {
    __shared__ int scnt[CN_], sbase[CN_];
    __shared__ int isLast;
    __shared__ int pfx[CN_ + 1];
    int t = threadIdx.x;
    if (t < CN_) scnt[t] = 0;
    __syncthreads();
    int r = blockIdx.x * 256 + t;
    int c = lab[r];
    int local = atomicAdd(&scnt[c], 1);
    __syncthreads();
    if (t < CN_) sbase[t] = atomicAdd(&g_cnt[t], scnt[t]);
    __syncthreads();
    g_idx[c * ROWS_ + sbase[c] + local] = r;

    // last-done block builds the compact tile list
    __threadfence();
    if (t == 0) isLast = (atomicAdd(&g_done, 1) == (int)gridDim.x - 1);
    __syncthreads();
    if (!isLast) return;
    if (t == 0) {
        int off = 0;
        for (int cc = 0; cc < CN_; cc++) {
            pfx[cc] = off;
            off += (g_cnt[cc] + TILE_M - 1) / TILE_M;
        }
        pfx[CN_] = off;
        g_nt = off;
    }
    __syncthreads();
    int nt = pfx[CN_];
    for (int i = t; i < nt; i += blockDim.x) {
        int cc = 0;
        while (cc < CN_ - 1 && i >= pfx[cc + 1]) cc++;
        g_tile[i] = make_int2(cc, (i - pfx[cc]) * TILE_M);
    }
}

// ---------------- L3: fused GEMM (blocks < NEI_B) + self embed (rest) ----------------
// nei smem: A' [64 x 104 halves] = 13312 B ; B[2][48 x 72 halves] = 2x6912 B
#define ASTR_H 104
#define BSTR_H 72

__global__ void __launch_bounds__(128, 6)
k_main(const float* __restrict__ neis,
       const float* __restrict__ bn,
       const float* __restrict__ obs,
       const float* __restrict__ Ws,
       const int*   __restrict__ slab,
       float*       __restrict__ outx,
       float*       __restrict__ outn) {
    __shared__ __half Ash[TILE_M * ASTR_H];     // 13312 B
    __shared__ __half Bsh[2][DNEI_ * BSTR_H];   // 13824 B
    int tid = threadIdx.x;

    if (blockIdx.x >= NEI_B) {
        // ---------------- self embedding: one batch row per block ----------------
        float* osf = (float*)Ash;               // reuse smem
        int b = blockIdx.x - NEI_B;
        if (tid < 12) ((float4*)osf)[tid] = ((const float4*)(obs + b * 48))[tid];
        int c = slab[b];
        __syncthreads();
        const float* W = Ws + c * DSELF_ * E_ + tid * 4;
        float4 acc = make_float4(0.f, 0.f, 0.f, 0.f);
#pragma unroll
        for (int j = 0; j < 48; j++) {
            float4 w = *(const float4*)(W + j * E_);
            float a = osf[j];
            acc.x += a * w.x; acc.y += a * w.y; acc.z += a * w.z; acc.w += a * w.w;
        }
        const float4* ap = (const float4*)(g_anchor + c * K_ * E_) + tid;
        float4* o = (float4*)(outx + b * K_ * E_) + tid;
#pragma unroll
        for (int k = 0; k < K_; k++) {
            float4 an = ap[k * (E_ / 4)];
            o[k * (E_ / 4)] = make_float4(acc.x + an.x, acc.y + an.y, acc.z + an.z, acc.w + an.w);
        }
        return;
    }

    // ---------------- neighbor GEMM tile ----------------
    if (blockIdx.x >= g_nt) return;
    int2 tl  = g_tile[blockIdx.x];
    int c    = tl.x;
    int base = tl.y;
    int cnt  = g_cnt[c];

    uint32_t sbA = smem_u32(Ash);
    uint32_t sbB = smem_u32(Bsh);

    // prefetch B[0] (e-chunk 0): 48 x 64 halves = 384 x 16B
    {
        const __half* gb = g_Bh + c * DNEI_ * E_;
#pragma unroll
        for (int p = 0; p < 3; p++) {
            int chunk = p * 128 + tid;
            int k  = chunk >> 3;
            int cc = chunk & 7;
            cpa16(sbB + k * (BSTR_H * 2) + cc * 16, gb + k * E_ + cc * 8);
        }
        CPA_COMMIT();
    }

    // A tile: gather + srecip + fp16 hi/lo split (once per CTA)
#pragma unroll
    for (int p = 0; p < 6; p++) {
        int lin = p * 128 + tid;          // 0..767
        int row = lin / 12;
        int v   = lin - row * 12;
        int gi  = base + row;
        float4 a = make_float4(0.f, 0.f, 0.f, 0.f);
        if (gi < cnt) {
            int rr = g_idx[c * ROWS_ + gi];
            a = ((const float4*)(neis + (long long)rr * 48))[v];
            a.x = srecip(a.x); a.y = srecip(a.y); a.z = srecip(a.z); a.w = srecip(a.w);
        }
        __half hx = __float2half_rn(a.x), hy = __float2half_rn(a.y);
        __half hz = __float2half_rn(a.z), hw = __float2half_rn(a.w);
        __half lx = __float2half_rn(a.x - __half2float(hx));
        __half ly = __float2half_rn(a.y - __half2float(hy));
        __half lz = __float2half_rn(a.z - __half2float(hz));
        __half lw = __float2half_rn(a.w - __half2float(hw));
        __half2* dst = (__half2*)(Ash + row * ASTR_H + v * 4);
        dst[0] = __halves2half2(hx, hy);
        dst[1] = __halves2half2(hz, hw);
        __half2* dstl = (__half2*)(Ash + row * ASTR_H + 48 + v * 4);
        dstl[0] = __halves2half2(lx, ly);
        dstl[1] = __halves2half2(lz, lw);
    }

    // lane mapping: 4 warps = 2(wm) x 2(wn), warp tile 32x32
    int w    = tid >> 5;
    int lane = tid & 31;
    int wm   = w >> 1;
    int wn   = w & 1;

    int rowL = wm * 32 + ((lane >> 3) & 1) * 8 + (lane & 7);
    int kLa  = (lane >> 4) * 8;
    uint32_t aLane = sbA + (uint32_t)(rowL * (ASTR_H * 2) + kLa * 2);
    int kLb = ((lane >> 3) & 1) * 8 + (lane & 7);
    int nLb = (lane >> 4) * 8;
    uint32_t bLaneBase = sbB + (uint32_t)(kLb * (BSTR_H * 2) + (wn * 32 + nLb) * 2);

    // epilogue row indices
    int qr = lane >> 2;
    int qc = (lane & 3) * 2;
    int rg_[4];
    bool val_[4];
#pragma unroll
    for (int mi = 0; mi < 2; mi++) {
#pragma unroll
        for (int hf = 0; hf < 2; hf++) {
            int gi = base + wm * 32 + mi * 16 + hf * 8 + qr;
            val_[mi * 2 + hf] = gi < cnt;
            rg_[mi * 2 + hf]  = (gi < cnt) ? g_idx[c * ROWS_ + gi] : 0;
        }
    }

    // loop over 8 e-chunks of 64
#pragma unroll
    for (int et = 0; et < 8; et++) {
        CPA_WAIT0();
        __syncthreads();

        if (et < 7) {
            const __half* gb = g_Bh + c * DNEI_ * E_ + (et + 1) * 64;
            uint32_t dstb = sbB + ((et + 1) & 1) * (DNEI_ * BSTR_H * 2);
#pragma unroll
            for (int p = 0; p < 3; p++) {
                int chunk = p * 128 + tid;
                int k  = chunk >> 3;
                int cc = chunk & 7;
                cpa16(dstb + k * (BSTR_H * 2) + cc * 16, gb + k * E_ + cc * 8);
            }
            CPA_COMMIT();
        }

        float acc[8][4];
#pragma unroll
        for (int i = 0; i < 8; i++) {
            acc[i][0] = 0.f; acc[i][1] = 0.f; acc[i][2] = 0.f; acc[i][3] = 0.f;
        }

        uint32_t bLane = bLaneBase + (et & 1) * (DNEI_ * BSTR_H * 2);
#pragma unroll
        for (int ks = 0; ks < 6; ks++) {
            int kb = (ks < 3) ? ks : (ks - 3);
            uint32_t af[2][4], bfr[2][4];
#pragma unroll
            for (int mi = 0; mi < 2; mi++)
                ldsm4(af[mi], aLane + mi * 16 * (ASTR_H * 2) + ks * 32);
#pragma unroll
            for (int ng = 0; ng < 2; ng++)
                ldsm4t(bfr[ng], bLane + kb * 16 * (BSTR_H * 2) + ng * 32);
#pragma unroll
            for (int mi = 0; mi < 2; mi++) {
#pragma unroll
                for (int ni = 0; ni < 4; ni++)
                    mma_f16(acc[mi * 4 + ni], af[mi],
                            bfr[ni >> 1][(ni & 1) * 2], bfr[ni >> 1][(ni & 1) * 2 + 1]);
            }
        }

        // epilogue
        int e0 = et << 6;
        const float* bp = bn + c * E_ + e0 + wn * 32 + qc;
        float bx[4], by[4];
#pragma unroll
        for (int ni = 0; ni < 4; ni++) { bx[ni] = bp[ni * 8]; by[ni] = bp[ni * 8 + 1]; }
#pragma unroll
        for (int mi = 0; mi < 2; mi++) {
#pragma unroll
            for (int hf = 0; hf < 2; hf++) {
                if (val_[mi * 2 + hf]) {
                    float* o = outn + (long long)rg_[mi * 2 + hf] * E_ + e0 + wn * 32 + qc;
#pragma unroll
                    for (int ni = 0; ni < 4; ni++) {
                        float2 v;
                        v.x = acc[mi * 4 + ni][hf * 2 + 0] + bx[ni];
                        v.y = acc[mi * 4 + ni][hf * 2 + 1] + by[ni];
                        *(float2*)(o + ni * 8) = v;
                    }
                }
            }
        }
    }
}

// ---------------- launch ----------------
extern "C" void kernel_launch(void* const* d_in, const int* in_sizes, int n_in,
                              void* d_out, int out_size) {
    const float* obs  = (const float*)d_in[0];
    const float* neis = (const float*)d_in[1];
    const float* it   = (const float*)d_in[2];
    const float* Ws   = (const float*)d_in[3];
    const float* bs   = (const float*)d_in[4];
    const float* Wn   = (const float*)d_in[5];
    const float* bn   = (const float*)d_in[6];
    const int*   slab = (const int*)d_in[7];
    const int*   nlab = (const int*)d_in[8];

    float* outx = (float*)d_out;            // [B, K, E]
    float* outn = outx + XSIZE_;            // [B, N, E]

    k_pre<<<C_ * K_ + CN_ * 8, 256>>>(it, Ws, bs, Wn);
    k_bucket<<<ROWS_ / 256, 256>>>(nlab);
    k_main<<<NEI_B + B_, 128>>>(neis, bn, obs, Ws, slab, outx, outn);
}

// round 9
// speedup vs baseline: 2.1026x; 1.1020x over previous
#include <cuda_runtime.h>
#include <cuda_fp16.h>
#include <cstdint>

#define EPS_ 1e-4f

#define B_     2048
#define N_     64
#define E_     512
#define C_     6
#define CN_    7
#define K_     20
#define DSELF_ 120
#define DNEI_  48
#define ROWS_  (B_ * N_)        /* 131072 */
#define XSIZE_ (B_ * K_ * E_)   /* 20971520 */

#define TILE_M 64
#define NEI_B  2056             /* >= sum ceil(cnt_c/64) = 2048+6 */

// ---------------- device scratch ----------------
__device__ float g_anchor[C_ * K_ * E_];
__device__ int   g_cnt[CN_];
__device__ int   g_idx[CN_ * ROWS_];
__device__ int   g_nt;
__device__ int   g_done;
__device__ int2  g_tile[NEI_B];
__device__ __half g_Bh[CN_ * DNEI_ * E_];    // fp16 weights [c][k][e]

// ---------------- helpers ----------------
__device__ __forceinline__ uint32_t smem_u32(const void* p) {
    uint32_t a;
    asm("{ .reg .u64 t; cvta.to.shared.u64 t, %1; cvt.u32.u64 %0, t; }" : "=r"(a) : "l"(p));
    return a;
}
__device__ __forceinline__ float srecip(float x) {
    float d = x + (x >= 0.0f ? EPS_ : -EPS_);
    return __fdividef(1.0f, d);
}
__device__ __forceinline__ void ldsm4(uint32_t (&r)[4], uint32_t addr) {
    asm volatile("ldmatrix.sync.aligned.m8n8.x4.shared.b16 {%0,%1,%2,%3}, [%4];"
                 : "=r"(r[0]), "=r"(r[1]), "=r"(r[2]), "=r"(r[3]) : "r"(addr));
}
__device__ __forceinline__ void ldsm4t(uint32_t (&r)[4], uint32_t addr) {
    asm volatile("ldmatrix.sync.aligned.m8n8.x4.trans.shared.b16 {%0,%1,%2,%3}, [%4];"
                 : "=r"(r[0]), "=r"(r[1]), "=r"(r[2]), "=r"(r[3]) : "r"(addr));
}
__device__ __forceinline__ void mma_f16(float (&d)[4], const uint32_t (&a)[4],
                                        uint32_t b0, uint32_t b1) {
    asm volatile("mma.sync.aligned.m16n8k16.row.col.f32.f16.f16.f32 "
                 "{%0,%1,%2,%3}, {%4,%5,%6,%7}, {%8,%9}, {%0,%1,%2,%3};"
                 : "+f"(d[0]), "+f"(d[1]), "+f"(d[2]), "+f"(d[3])
                 : "r"(a[0]), "r"(a[1]), "r"(a[2]), "r"(a[3]), "r"(b0), "r"(b1));
}
__device__ __forceinline__ void cpa16(uint32_t dst, const void* src) {
    asm volatile("cp.async.cg.shared.global [%0], [%1], 16;" :: "r"(dst), "l"(src) : "memory");
}
#define CPA_COMMIT() asm volatile("cp.async.commit_group;" ::: "memory")
#define CPA_WAIT0()  asm volatile("cp.async.wait_group 0;" ::: "memory")

// ---------------- L1: anchors + weight fp16 convert + zero flags ----------------
__global__ void k_pre(const float* __restrict__ it,
                      const float* __restrict__ Ws,
                      const float* __restrict__ bs,
                      const float* __restrict__ Wn) {
    int blk = blockIdx.x;
    int t   = threadIdx.x;
    if (blk < C_ * K_) {
        if (blk == 0 && t < CN_) g_cnt[t] = 0;
        if (blk == 0 && t == CN_) g_done = 0;
        __shared__ float its[72];
        int ck = blk;
        int c  = ck / K_;
        if (t < 18) ((float4*)its)[t] = ((const float4*)(it + ck * 72))[t];
        __syncthreads();
#pragma unroll
        for (int h = 0; h < 2; h++) {
            int e = t + h * 256;
            const float* W = Ws + c * DSELF_ * E_ + 48 * E_ + e;
            float a0 = 0.f, a1 = 0.f, a2 = 0.f, a3 = 0.f;
#pragma unroll
            for (int j = 0; j < 72; j += 4) {
                a0 += its[j + 0] * W[(j + 0) * E_];
                a1 += its[j + 1] * W[(j + 1) * E_];
                a2 += its[j + 2] * W[(j + 2) * E_];
                a3 += its[j + 3] * W[(j + 3) * E_];
            }
            g_anchor[ck * E_ + e] = (a0 + a1) + (a2 + a3) + bs[c * E_ + e];
        }
    } else {
        int pb = blk - C_ * K_;
        int c  = pb >> 3;
        int s  = pb & 7;
        const float* src = Wn + c * DNEI_ * E_;
        __half* dst = g_Bh + c * DNEI_ * E_;
        int base = s * 3072;
#pragma unroll
        for (int q = 0; q < 12; q++) {
            int i = base + q * 256 + t;
            dst[i] = __float2half_rn(src[i]);
        }
    }
}

// ---------------- L2: bucket rows + last block builds tile list ----------------
__global__ void k_bucket(const int* __restrict__ lab) {
    __shared__ int scnt[CN_], sbase[CN_];
    __shared__ int isLast;
    __shared__ int pfx[CN_ + 1];
    int t = threadIdx.x;
    if (t < CN_) scnt[t] = 0;
    __syncthreads();
    int r = blockIdx.x * 256 + t;
    int c = lab[r];
    int local = atomicAdd(&scnt[c], 1);
    __syncthreads();
    if (t < CN_) sbase[t] = atomicAdd(&g_cnt[t], scnt[t]);
    __syncthreads();
    g_idx[c * ROWS_ + sbase[c] + local] = r;

    __threadfence();
    if (t == 0) isLast = (atomicAdd(&g_done, 1) == (int)gridDim.x - 1);
    __syncthreads();
    if (!isLast) return;
    if (t == 0) {
        int off = 0;
        for (int cc = 0; cc < CN_; cc++) {
            pfx[cc] = off;
            off += (g_cnt[cc] + TILE_M - 1) / TILE_M;
        }
        pfx[CN_] = off;
        g_nt = off;
    }
    __syncthreads();
    int nt = pfx[CN_];
    for (int i = t; i < nt; i += blockDim.x) {
        int cc = 0;
        while (cc < CN_ - 1 && i >= pfx[cc + 1]) cc++;
        g_tile[i] = make_int2(cc, (i - pfx[cc]) * TILE_M);
    }
}

// ---------------- L3: fused GEMM (blocks < NEI_B) + self embed (rest) ----------------
// nei smem: A [64 x 56 halves] = 7168 B ; B[2][48 x 72 halves] = 2x6912 B
#define ASTR_H 56
#define BSTR_H 72

__global__ void __launch_bounds__(128, 7)
k_main(const float* __restrict__ neis,
       const float* __restrict__ bn,
       const float* __restrict__ obs,
       const float* __restrict__ Ws,
       const int*   __restrict__ slab,
       float*       __restrict__ outx,
       float*       __restrict__ outn) {
    __shared__ __half Ash[TILE_M * ASTR_H];     // 7168 B
    __shared__ __half Bsh[2][DNEI_ * BSTR_H];   // 13824 B
    int tid = threadIdx.x;

    if (blockIdx.x >= NEI_B) {
        // ---------------- self embedding: one batch row per block ----------------
        float* osf = (float*)Ash;               // reuse smem
        int b = blockIdx.x - NEI_B;
        if (tid < 12) ((float4*)osf)[tid] = ((const float4*)(obs + b * 48))[tid];
        int c = slab[b];
        __syncthreads();
        const float* W = Ws + c * DSELF_ * E_ + tid * 4;
        float4 acc = make_float4(0.f, 0.f, 0.f, 0.f);
#pragma unroll
        for (int j = 0; j < 48; j++) {
            float4 w = *(const float4*)(W + j * E_);
            float a = osf[j];
            acc.x += a * w.x; acc.y += a * w.y; acc.z += a * w.z; acc.w += a * w.w;
        }
        const float4* ap = (const float4*)(g_anchor + c * K_ * E_) + tid;
        float4* o = (float4*)(outx + b * K_ * E_) + tid;
#pragma unroll
        for (int k = 0; k < K_; k++) {
            float4 an = ap[k * (E_ / 4)];
            o[k * (E_ / 4)] = make_float4(acc.x + an.x, acc.y + an.y, acc.z + an.z, acc.w + an.w);
        }
        return;
    }

    // ---------------- neighbor GEMM tile ----------------
    if (blockIdx.x >= g_nt) return;
    int2 tl  = g_tile[blockIdx.x];
    int c    = tl.x;
    int base = tl.y;
    int cnt  = g_cnt[c];

    uint32_t sbA = smem_u32(Ash);
    uint32_t sbB = smem_u32(Bsh);

    // prefetch B[0] (e-chunk 0): 48 x 64 halves = 384 x 16B
    {
        const __half* gb = g_Bh + c * DNEI_ * E_;
#pragma unroll
        for (int p = 0; p < 3; p++) {
            int chunk = p * 128 + tid;
            int k  = chunk >> 3;
            int cc = chunk & 7;
            cpa16(sbB + k * (BSTR_H * 2) + cc * 16, gb + k * E_ + cc * 8);
        }
        CPA_COMMIT();
    }

    // A tile: gather + srecip + single fp16 (once per CTA)
#pragma unroll
    for (int p = 0; p < 6; p++) {
        int lin = p * 128 + tid;          // 0..767
        int row = lin / 12;
        int v   = lin - row * 12;
        int gi  = base + row;
        float4 a = make_float4(0.f, 0.f, 0.f, 0.f);
        if (gi < cnt) {
            int rr = g_idx[c * ROWS_ + gi];
            a = ((const float4*)(neis + (long long)rr * 48))[v];
            a.x = srecip(a.x); a.y = srecip(a.y); a.z = srecip(a.z); a.w = srecip(a.w);
        }
        __half2* dst = (__half2*)(Ash + row * ASTR_H + v * 4);
        dst[0] = __halves2half2(__float2half_rn(a.x), __float2half_rn(a.y));
        dst[1] = __halves2half2(__float2half_rn(a.z), __float2half_rn(a.w));
    }

    // lane mapping: 4 warps = 2(wm) x 2(wn), warp tile 32x32
    int w    = tid >> 5;
    int lane = tid & 31;
    int wm   = w >> 1;
    int wn   = w & 1;

    int rowL = wm * 32 + ((lane >> 3) & 1) * 8 + (lane & 7);
    int kLa  = (lane >> 4) * 8;
    uint32_t aLane = sbA + (uint32_t)(rowL * (ASTR_H * 2) + kLa * 2);
    int kLb = ((lane >> 3) & 1) * 8 + (lane & 7);
    int nLb = (lane >> 4) * 8;
    uint32_t bLaneBase = sbB + (uint32_t)(kLb * (BSTR_H * 2) + (wn * 32 + nLb) * 2);

    // epilogue row indices
    int qr = lane >> 2;
    int qc = (lane & 3) * 2;
    int rg_[4];
    bool val_[4];
#pragma unroll
    for (int mi = 0; mi < 2; mi++) {
#pragma unroll
        for (int hf = 0; hf < 2; hf++) {
            int gi = base + wm * 32 + mi * 16 + hf * 8 + qr;
            val_[mi * 2 + hf] = gi < cnt;
            rg_[mi * 2 + hf]  = (gi < cnt) ? g_idx[c * ROWS_ + gi] : 0;
        }
    }

    // loop over 8 e-chunks of 64
#pragma unroll
    for (int et = 0; et < 8; et++) {
        CPA_WAIT0();
        __syncthreads();

        if (et < 7) {
            const __half* gb = g_Bh + c * DNEI_ * E_ + (et + 1) * 64;
            uint32_t dstb = sbB + ((et + 1) & 1) * (DNEI_ * BSTR_H * 2);
#pragma unroll
            for (int p = 0; p < 3; p++) {
                int chunk = p * 128 + tid;
                int k  = chunk >> 3;
                int cc = chunk & 7;
                cpa16(dstb + k * (BSTR_H * 2) + cc * 16, gb + k * E_ + cc * 8);
            }
            CPA_COMMIT();
        }

        float acc[8][4];
#pragma unroll
        for (int i = 0; i < 8; i++) {
            acc[i][0] = 0.f; acc[i][1] = 0.f; acc[i][2] = 0.f; acc[i][3] = 0.f;
        }

        uint32_t bLane = bLaneBase + (et & 1) * (DNEI_ * BSTR_H * 2);
#pragma unroll
        for (int ks = 0; ks < 3; ks++) {
            uint32_t af[2][4], bfr[2][4];
#pragma unroll
            for (int mi = 0; mi < 2; mi++)
                ldsm4(af[mi], aLane + mi * 16 * (ASTR_H * 2) + ks * 32);
#pragma unroll
            for (int ng = 0; ng < 2; ng++)
                ldsm4t(bfr[ng], bLane + ks * 16 * (BSTR_H * 2) + ng * 32);
#pragma unroll
            for (int mi = 0; mi < 2; mi++) {
#pragma unroll
                for (int ni = 0; ni < 4; ni++)
                    mma_f16(acc[mi * 4 + ni], af[mi],
                            bfr[ni >> 1][(ni & 1) * 2], bfr[ni >> 1][(ni & 1) * 2 + 1]);
            }
        }

        // epilogue
        int e0 = et << 6;
        const float* bp = bn + c * E_ + e0 + wn * 32 + qc;
        float bx[4], by[4];
#pragma unroll
        for (int ni = 0; ni < 4; ni++) { bx[ni] = bp[ni * 8]; by[ni] = bp[ni * 8 + 1]; }
#pragma unroll
        for (int mi = 0; mi < 2; mi++) {
#pragma unroll
            for (int hf = 0; hf < 2; hf++) {
                if (val_[mi * 2 + hf]) {
                    float* o = outn + (long long)rg_[mi * 2 + hf] * E_ + e0 + wn * 32 + qc;
#pragma unroll
                    for (int ni = 0; ni < 4; ni++) {
                        float2 v;
                        v.x = acc[mi * 4 + ni][hf * 2 + 0] + bx[ni];
                        v.y = acc[mi * 4 + ni][hf * 2 + 1] + by[ni];
                        *(float2*)(o + ni * 8) = v;
                    }
                }
            }
        }
    }
}

// ---------------- launch ----------------
extern "C" void kernel_launch(void* const* d_in, const int* in_sizes, int n_in,
                              void* d_out, int out_size) {
    const float* obs  = (const float*)d_in[0];
    const float* neis = (const float*)d_in[1];
    const float* it   = (const float*)d_in[2];
    const float* Ws   = (const float*)d_in[3];
    const float* bs   = (const float*)d_in[4];
    const float* Wn   = (const float*)d_in[5];
    const float* bn   = (const float*)d_in[6];
    const int*   slab = (const int*)d_in[7];
    const int*   nlab = (const int*)d_in[8];

    float* outx = (float*)d_out;            // [B, K, E]
    float* outn = outx + XSIZE_;            // [B, N, E]

    k_pre<<<C_ * K_ + CN_ * 8, 256>>>(it, Ws, bs, Wn);
    k_bucket<<<ROWS_ / 256, 256>>>(nlab);
    k_main<<<NEI_B + B_, 128>>>(neis, bn, obs, Ws, slab, outx, outn);
}